// round 13
// baseline (speedup 1.0000x reference)
#include <cuda_runtime.h>

#define WL_L      2048
#define WL_LMASK  2047
#define WL_D      32
#define WL_B      16
#define WL_NT     128                 // 2 planes × 64 threads (2 warps/plane)

#define WL_G      2                   // d-planes per CTA
#define WL_T      512                 // outputs per plane per CTA
#define WL_HALO   112                 // >= 105 back-reach, multiple of 4
#define WL_EXT    (WL_T + WL_HALO)    // 624 floats = 156 quads
#define WL_NCHUNK (WL_L / WL_T)       // 4
#define WL_NDG    (WL_D / WL_G)       // 16
#define WL_OQ     (WL_T / 4)          // 128 output quads per plane

#define PLANE_BAR(pl) asm volatile("bar.sync %0, 64;" :: "r"((pl) + 1) : "memory")

__global__ __launch_bounds__(WL_NT) void wavelet_db4_kernel(
    const float* __restrict__ x,       // (B, L, D)
    const float* __restrict__ w_dec,   // (4, L, L) — only 8 taps read
    const float* __restrict__ v_dec,   // (4, L, L) — only 8 taps read
    float* __restrict__ out)           // (B, D, L, 5)
{
    __shared__ __align__(16) float xs [WL_G][WL_EXT];
    __shared__ __align__(16) float v0s[WL_G][WL_EXT];
    __shared__ __align__(16) float v1s[WL_G][WL_EXT];
    __shared__ __align__(16) float v2s[WL_G][WL_EXT];
    __shared__ float4 ws[WL_G][3][WL_OQ];   // staged w0,w1,w2 quads
    __shared__ float gs[8];
    __shared__ float hs[8];

    const int tid   = threadIdx.x;
    const int blk   = blockIdx.x;
    const int chunk = blk & (WL_NCHUNK - 1);
    const int dg    = (blk >> 2) & (WL_NDG - 1);
    const int b     = blk >> 6;
    const int M0    = chunk * WL_T;
    const int base  = M0 - WL_HALO;

    const int p  = tid >> 6;          // plane 0..1 (64 threads = 2 warps each)
    const int pq = tid & 63;          // slot in plane 0..63
    const int q0 = 28 + 2 * pq;       // first of this thread's two adjacent quads
    const int hq = pq - 36;           // halo quad 0..27 on pq 36..63

    // taps from row 0 of level-0 filters: f[0][0][(0-i) mod L] = tap[i]
    if (tid < 8) {
        int col = (WL_L - tid) & WL_LMASK;
        gs[tid] = v_dec[col];
        hs[tid] = w_dec[col];
    }

    // gather: 2 adjacent d per x-row (one LDG.64 per row)
    {
        const float* xp = x + ((size_t)b * WL_L * WL_D) + dg * WL_G;
        #pragma unroll
        for (int l = tid; l < WL_EXT; l += WL_NT) {
            int gl = (base + l) & WL_LMASK;
            float2 qv = *(const float2*)(xp + (size_t)gl * WL_D);
            xs[0][l] = qv.x; xs[1][l] = qv.y;
        }
    }
    __syncthreads();   // the ONLY CTA-wide barrier

    float g[8], h[8];
    #pragma unroll
    for (int i = 0; i < 8; i++) { g[i] = gs[i]; h[i] = hs[i]; }

    const float4* xs4  = (const float4*)(&xs [p][0]);
    const float4* v0s4 = (const float4*)(&v0s[p][0]);
    const float4* v1s4 = (const float4*)(&v1s[p][0]);
    const float4* v2s4 = (const float4*)(&v2s[p][0]);
    float4* v0s4w = (float4*)(&v0s[p][0]);
    float4* v1s4w = (float4*)(&v1s[p][0]);
    float4* v2s4w = (float4*)(&v2s[p][0]);

    // ── stage 1: dilation 1 on xs → v0 (g) + w0 (h→ws[0]); shared 16-float window
    {
        float win[16];
        #pragma unroll
        for (int kk = 0; kk < 4; kk++) {
            float4 qv = xs4[q0 - 2 + kk];
            win[4*kk] = qv.x; win[4*kk+1] = qv.y; win[4*kk+2] = qv.z; win[4*kk+3] = qv.w;
        }
        float vg[8], vh[8];
        #pragma unroll
        for (int j = 0; j < 8; j++) { vg[j] = 0.f; vh[j] = 0.f; }
        #pragma unroll
        for (int i = 0; i < 8; i++) {
            #pragma unroll
            for (int j = 0; j < 8; j++) {
                vg[j] += g[i] * win[8 + j - i];
                vh[j] += h[i] * win[8 + j - i];
            }
        }
        v0s4w[q0]     = make_float4(vg[0], vg[1], vg[2], vg[3]);
        v0s4w[q0 + 1] = make_float4(vg[4], vg[5], vg[6], vg[7]);
        ws[p][0][2*pq]     = make_float4(vh[0], vh[1], vh[2], vh[3]);
        ws[p][0][2*pq + 1] = make_float4(vh[4], vh[5], vh[6], vh[7]);

        if (hq >= 2) {                // halo v0 (g only), quads 2..27
            float hw[12];
            #pragma unroll
            for (int kk = 0; kk < 3; kk++) {
                float4 qv = xs4[hq - 2 + kk];
                hw[4*kk] = qv.x; hw[4*kk+1] = qv.y; hw[4*kk+2] = qv.z; hw[4*kk+3] = qv.w;
            }
            float a0=0.f, a1=0.f, a2=0.f, a3=0.f;
            #pragma unroll
            for (int i = 0; i < 8; i++) {
                a0 += g[i] * hw[ 8 - i]; a1 += g[i] * hw[ 9 - i];
                a2 += g[i] * hw[10 - i]; a3 += g[i] * hw[11 - i];
            }
            v0s4w[hq] = make_float4(a0, a1, a2, a3);
        }
    }
    PLANE_BAR(p);

    // ── stage 2: dilation 2 on v0 → v1 (g) + w1 (h→ws[1]); shared 24-float window
    {
        float win[24];
        #pragma unroll
        for (int kk = 0; kk < 6; kk++) {
            float4 qv = v0s4[q0 - 4 + kk];
            win[4*kk] = qv.x; win[4*kk+1] = qv.y; win[4*kk+2] = qv.z; win[4*kk+3] = qv.w;
        }
        float vg[8], vh[8];
        #pragma unroll
        for (int j = 0; j < 8; j++) { vg[j] = 0.f; vh[j] = 0.f; }
        #pragma unroll
        for (int i = 0; i < 8; i++) {
            #pragma unroll
            for (int j = 0; j < 8; j++) {
                vg[j] += g[i] * win[16 + j - 2*i];
                vh[j] += h[i] * win[16 + j - 2*i];
            }
        }
        v1s4w[q0]     = make_float4(vg[0], vg[1], vg[2], vg[3]);
        v1s4w[q0 + 1] = make_float4(vg[4], vg[5], vg[6], vg[7]);
        ws[p][1][2*pq]     = make_float4(vh[0], vh[1], vh[2], vh[3]);
        ws[p][1][2*pq + 1] = make_float4(vh[4], vh[5], vh[6], vh[7]);

        if (hq >= 7) {                // halo v1 (g only), quads 7..27
            float hw[20];
            #pragma unroll
            for (int kk = 0; kk < 5; kk++) {
                float4 qv = v0s4[hq - 4 + kk];
                hw[4*kk] = qv.x; hw[4*kk+1] = qv.y; hw[4*kk+2] = qv.z; hw[4*kk+3] = qv.w;
            }
            float a0=0.f, a1=0.f, a2=0.f, a3=0.f;
            #pragma unroll
            for (int i = 0; i < 8; i++) {
                a0 += g[i] * hw[16 - 2*i]; a1 += g[i] * hw[17 - 2*i];
                a2 += g[i] * hw[18 - 2*i]; a3 += g[i] * hw[19 - 2*i];
            }
            v1s4w[hq] = make_float4(a0, a1, a2, a3);
        }
    }
    PLANE_BAR(p);

    // ── stage 3: dilation 4 on v1 → v2 (g) + w2 (h→ws[2]); per-quad float4/tap
    {
        #pragma unroll
        for (int s = 0; s < 2; s++) {
            const int q = q0 + s;
            float vg[4] = {0,0,0,0}, vh[4] = {0,0,0,0};
            #pragma unroll
            for (int i = 0; i < 8; i++) {
                float4 qv = v1s4[q - i];
                vg[0] += g[i] * qv.x; vg[1] += g[i] * qv.y;
                vg[2] += g[i] * qv.z; vg[3] += g[i] * qv.w;
                vh[0] += h[i] * qv.x; vh[1] += h[i] * qv.y;
                vh[2] += h[i] * qv.z; vh[3] += h[i] * qv.w;
            }
            v2s4w[q]           = make_float4(vg[0], vg[1], vg[2], vg[3]);
            ws[p][2][2*pq + s] = make_float4(vh[0], vh[1], vh[2], vh[3]);
        }
        if (hq >= 14) {               // halo v2 (g only), quads 14..27
            float a0=0.f, a1=0.f, a2=0.f, a3=0.f;
            #pragma unroll
            for (int i = 0; i < 8; i++) {
                float4 qv = v1s4[hq - i];
                a0 += g[i] * qv.x; a1 += g[i] * qv.y;
                a2 += g[i] * qv.z; a3 += g[i] * qv.w;
            }
            v2s4w[hq] = make_float4(a0, a1, a2, a3);
        }
    }
    PLANE_BAR(p);

    // ── stage 4: dilation 8 on v2 → w3 (h) + v3 (g); per quad, pack 5 coeffs
    {
        const int bd = b * WL_D + dg * WL_G + p;
        #pragma unroll
        for (int s = 0; s < 2; s++) {
            const int q  = q0 + s;
            const int oq = 2 * pq + s;
            float w3[4] = {0,0,0,0}, v3[4] = {0,0,0,0};
            #pragma unroll
            for (int i = 0; i < 8; i++) {
                float4 qv = v2s4[q - 2*i];
                w3[0] += h[i] * qv.x; w3[1] += h[i] * qv.y;
                w3[2] += h[i] * qv.z; w3[3] += h[i] * qv.w;
                v3[0] += g[i] * qv.x; v3[1] += g[i] * qv.y;
                v3[2] += g[i] * qv.z; v3[3] += g[i] * qv.w;
            }
            float4 w0q = ws[p][0][oq];
            float4 w1q = ws[p][1][oq];
            float4 w2q = ws[p][2][oq];
            float w0[4] = {w0q.x, w0q.y, w0q.z, w0q.w};
            float w1[4] = {w1q.x, w1q.y, w1q.z, w1q.w};
            float w2[4] = {w2q.x, w2q.y, w2q.z, w2q.w};

            float o[20];
            #pragma unroll
            for (int j = 0; j < 4; j++) {
                o[j*5 + 0] = w0[j];
                o[j*5 + 1] = w1[j];
                o[j*5 + 2] = w2[j];
                o[j*5 + 3] = w3[j];
                o[j*5 + 4] = v3[j];
            }
            const int m0 = M0 + 4 * oq;
            float4* og = (float4*)(out + ((size_t)bd * WL_L + m0) * 5);
            #pragma unroll
            for (int kk = 0; kk < 5; kk++) og[kk] = ((const float4*)o)[kk];
        }
    }
}

extern "C" void kernel_launch(void* const* d_in, const int* in_sizes, int n_in,
                              void* d_out, int out_size) {
    const float* x     = (const float*)d_in[0];
    const float* w_dec = (const float*)d_in[1];
    const float* v_dec = (const float*)d_in[2];
    float* out = (float*)d_out;

    wavelet_db4_kernel<<<WL_B * WL_NDG * WL_NCHUNK, WL_NT>>>(x, w_dec, v_dec, out);
}